// round 8
// baseline (speedup 1.0000x reference)
#include <cuda_runtime.h>
#include <math.h>

#define NATOMS 65536
#define NM     6
#define LL     7
#define NC     (NM*LL*LL)   // 294
#define RCF    6.0f
#define RCINV  (1.0f/6.0f)

// pass1: 2 threads per atom, 64 atoms per 128-thread block
#define TPB1   128
#define APB    64
#define NBLK1  (NATOMS/APB)   // 1024

// pass2: 1 atom per thread, 128 atoms per block
#define TPB2   128
#define NBLK2  (NATOMS/TPB2)  // 512

__device__ float  g_part[NBLK1 * NC];
__device__ float  g_c[NC];
__device__ float4 g_coef4[LL*NM*LL*2];   // [l][b][m] x {wr,wi,cxr,cxi | cyr,cyi,czr,czi}

// ---------------------------------------------------------------------------
// Value-row recursion step: dest holds row lv-2, overwritten in place.
// ---------------------------------------------------------------------------
#define V_STEP(lv, RS, IS, RD, ID) do {                                        \
    _Pragma("unroll")                                                          \
    for (int m = 0; m < lv-1; m++){                                            \
        const float invA =                                                     \
            rsqrtf((float)(lv*lv - m*m)/((2.0f*lv-1.0f)*(2.0f*lv+1.0f)));      \
        const float Ap = sqrtf((float)((lv-1)*(lv-1) - m*m)/                   \
                               ((2.0f*lv-3.0f)*(2.0f*lv-1.0f)));               \
        const float o_r = RD[m], o_i = ID[m];                                  \
        RD[m] = (z*RS[m] - Ap*r2*o_r)*invA;                                    \
        ID[m] = (z*IS[m] - Ap*r2*o_i)*invA;                                    \
    }                                                                          \
    {   const int m = lv-1;                                                    \
        const float invA =                                                     \
            rsqrtf((float)(lv*lv - m*m)/((2.0f*lv-1.0f)*(2.0f*lv+1.0f)));      \
        RD[m] = z*RS[m]*invA;                                                  \
        ID[m] = z*IS[m]*invA;                                                  \
    }                                                                          \
    {   const float alc = -sqrtf((2.0f*lv + 1.0f)/(2.0f*lv));                  \
        RD[lv] = alc*(x*RS[lv-1] - y*IS[lv-1]);                                \
        ID[lv] = alc*(x*IS[lv-1] + y*RS[lv-1]);                                \
    }                                                                          \
} while(0)

// ---------------------------------------------------------------------------
// Pass 1: values-only recursion; single-stage warp reduction (16 partials).
// ---------------------------------------------------------------------------
#define P1_RED(val, idx) do {                                                  \
    float _v = (val);                                                          \
    _v += __shfl_xor_sync(0xffffffffu, _v, 16);                                \
    if (lane < 16) wsh[wloc][lane][idx] = _v;                                  \
} while(0)

#define V_EMIT(lv, RD, ID) do {                                                \
    _Pragma("unroll")                                                          \
    for (int m = 0; m <= lv; m++){                                             \
        const float yv = RD[m];                                                \
        _Pragma("unroll")                                                      \
        for (int bb = 0; bb < 3; bb++)                                         \
            P1_RED(fh[bb]*yv, vb + bb*49 + lv*7 + (lv-m));                     \
    }                                                                          \
    _Pragma("unroll")                                                          \
    for (int m = 1; m <= lv; m++){                                             \
        const float yv = ID[m];                                                \
        _Pragma("unroll")                                                      \
        for (int bb = 0; bb < 3; bb++)                                         \
            P1_RED(fh[bb]*yv, vb + bb*49 + (m-1)*7 + lv);                      \
    }                                                                          \
} while(0)

__global__ void __launch_bounds__(TPB1) pass1(const float* __restrict__ xyz){
    __shared__ float wsh[2][16][NC];
    const int t    = threadIdx.x;
    const int lane = t & 31;
    const int half = t >> 6;
    const int al   = t & 63;
    const int wloc = al >> 5;
    const int vb   = half*3*49;
    const int j = blockIdx.x * APB + al;

    const float x = xyz[3*j+0], y = xyz[3*j+1], z = xyz[3*j+2];
    const float r2 = x*x + y*y + z*z;
    const float d  = sqrtf(r2);
    const float tc = 1.0f - d*RCINV;
    const float rcut = (d < RCF) ? tc*tc : 0.0f;

    float fh[3];
    {
        const float r6 = r2*r2*r2;
        fh[0] = rcut * (half ? r6 : 1.0f);
        fh[1] = fh[0]*r2;
        fh[2] = fh[1]*r2;
    }

    float RA[LL], IA[LL], RB[LL], IB[LL];
    RA[0] = 0.28209479177387814f; IA[0] = 0.0f;
    V_EMIT(0, RA, IA);
    {
        const float sq3 = 1.7320508075688772f;
        RB[0] = z*RA[0]*sq3;
        IB[0] = 0.0f;
        const float alc = -1.2247448713915890f;
        RB[1] = alc*(x*RA[0]);
        IB[1] = alc*(y*RA[0]);
    }
    V_EMIT(1, RB, IB);
    V_STEP(2, RB, IB, RA, IA); V_EMIT(2, RA, IA);
    V_STEP(3, RA, IA, RB, IB); V_EMIT(3, RB, IB);
    V_STEP(4, RB, IB, RA, IA); V_EMIT(4, RA, IA);
    V_STEP(5, RA, IA, RB, IB); V_EMIT(5, RB, IB);
    V_STEP(6, RB, IB, RA, IA); V_EMIT(6, RA, IA);

    __syncthreads();
    for (int v = t; v < NC; v += TPB1){
        float s = 0.0f;
        #pragma unroll
        for (int w = 0; w < 2; w++)
            #pragma unroll
            for (int c = 0; c < 16; c++)
                s += wsh[w][c][v];
        g_part[blockIdx.x*NC + v] = s;
    }
}

// ---------------------------------------------------------------------------
// Reduce partials -> c, compute p, and precompute per-(l,b,m) coefficient
// 8-tuples that fold mask weights + gradient lowering into pass2's FMA loop.
// ---------------------------------------------------------------------------
__global__ void __launch_bounds__(1024) reduce_c(float* __restrict__ out){
    __shared__ float part3[NC*3];
    __shared__ float csh[NC];
    const int t = threadIdx.x;
    if (t < NC*3){
        const int o = t/3, s = t%3;
        float sum = 0.0f;
        for (int p = s; p < NBLK1; p += 3) sum += g_part[p*NC + o];
        part3[t] = sum;
    }
    __syncthreads();
    if (t < NC){
        const float s = part3[t*3] + part3[t*3+1] + part3[t*3+2];
        g_c[t] = s;
        csh[t] = s;
    }
    __syncthreads();
    if (t < LL*NM*NM){   // 252: p output
        const int l = t / 36;
        const int a = (t / 6) % 6;
        const int b = t % 6;
        const float* ca = &csh[a*49];
        const float* cb = &csh[b*49];
        float s = 0.0f;
        for (int m = 0; m <= l; m++){
            const float w = (m == l) ? 1.0f : 2.0f;
            s += w * ca[l*7 + m] * cb[l*7 + m];
        }
        for (int lp = 0; lp < l; lp++){
            s += 2.0f * ca[lp*7 + l] * cb[lp*7 + l];
        }
        out[t] = s;
    }
    // coefficient scatter: one thread per (l,b)
    if (t < LL*NM){
        const int l = t / 6, b = t % 6;
        float C[7][8];
        #pragma unroll
        for (int m = 0; m < 7; m++)
            #pragma unroll
            for (int q = 0; q < 8; q++) C[m][q] = 0.0f;

        for (int m = 0; m <= l; m++){
            const float wr = ((m==0)?1.0f:2.0f) * csh[b*49 + l*7 + (l-m)];
            const float wi = (m>=1) ? 2.0f*csh[b*49 + (m-1)*7 + l] : 0.0f;
            C[m][0] += wr; C[m][1] += wi;
            const float az  = (m <= l-1)
                ? sqrtf((float)((l-m)*(l+m))*(2.0f*l+1.0f)/(2.0f*l-1.0f)) : 0.0f;
            const float apH = (m+1 <= l-1)
                ? 0.5f*sqrtf((float)((l-m)*(l-m-1))*(2.0f*l+1.0f)/(2.0f*l-1.0f)) : 0.0f;
            const float amH = (l >= 1 && (m >= 1 || l >= 2))
                ? 0.5f*sqrtf((float)((l+m)*(l+m-1))*(2.0f*l+1.0f)/(2.0f*l-1.0f)) : 0.0f;
            // Hz += wr*az*PR[m] + wi*az*PI[m]
            if (m <= l-1){ C[m][6] += wr*az; C[m][7] += wi*az; }
            // Hx += wr*(apH*PR[m+1]-amH*PRm1) + wi*(apH*PI[m+1]-amH*PIm1)
            // Hy += wr*(apH*PI[m+1]+amH*PIm1) - wi*(apH*PR[m+1]+amH*PRm1)
            if (m+1 <= l-1){
                C[m+1][2] += wr*apH;   // cxr
                C[m+1][3] += wi*apH;   // cxi
                C[m+1][5] += wr*apH;   // cyi
                C[m+1][4] -= wi*apH;   // cyr
            }
            if (m >= 1){
                C[m-1][2] -= wr*amH;
                C[m-1][3] -= wi*amH;
                C[m-1][5] += wr*amH;
                C[m-1][4] -= wi*amH;
            } else if (l >= 2){
                // PRm1 = -PR[1], PIm1 = +PI[1]; wi(0)=0 terms drop
                C[1][2] += wr*amH;
                C[1][5] += wr*amH;
            }
        }
        #pragma unroll
        for (int m = 0; m < 7; m++){
            g_coef4[((l*6+b)*7+m)*2+0] = make_float4(C[m][0],C[m][1],C[m][2],C[m][3]);
            g_coef4[((l*6+b)*7+m)*2+1] = make_float4(C[m][4],C[m][5],C[m][6],C[m][7]);
        }
    }
}

// ---------------------------------------------------------------------------
// Pass 2: values-only ping-pong recursion; G/H from precomputed coefficients;
// warp-private smem staging -> float4 streaming stores. No block barriers.
// ---------------------------------------------------------------------------
__device__ __forceinline__ int pair_idx(int a, int b){
    return a*6 - (a*(a+1))/2 + b;
}

#define D_EMIT2(lv, CR, CI, PR, PI) do {                                       \
    float G[6], Hx[6], Hy[6], Hz[6];                                           \
    _Pragma("unroll")                                                          \
    for (int b = 0; b < 6; b++){                                               \
        float g = 0.f, hx = 0.f, hy = 0.f, hz = 0.f;                           \
        _Pragma("unroll")                                                      \
        for (int m = 0; m <= lv; m++){                                         \
            const float4 c0 = coefsh[((lv*6+b)*7+m)*2+0];                      \
            const float4 c1 = coefsh[((lv*6+b)*7+m)*2+1];                      \
            g  += c0.x*CR[m] + c0.y*CI[m];                                     \
            hx += c0.z*PR[m] + c0.w*PI[m];                                     \
            hy += c1.x*PR[m] + c1.y*PI[m];                                     \
            hz += c1.z*PR[m] + c1.w*PI[m];                                     \
        }                                                                      \
        G[b] = g; Hx[b] = hx; Hy[b] = hy; Hz[b] = hz;                          \
    }                                                                          \
    __syncwarp();                                                              \
    /* stage 21 unique pairs (warp-private) */                                 \
    float pa = 1.0f;                                                           \
    _Pragma("unroll")                                                          \
    for (int a = 0; a < 6; a++){                                               \
        const float fa  = rcut*pa;                                             \
        const float dca = pa*(drc + (2.0f*a)*rcut*invd);                       \
        float pb = pa;                                                         \
        _Pragma("unroll")                                                      \
        for (int b = a; b < 6; b++){                                           \
            const float fb  = rcut*pb;                                         \
            const float dcb = pb*(drc + (2.0f*b)*rcut*invd);                   \
            const float s  = dca*G[b] + dcb*G[a];                              \
            float* sp = &stage[warp][pair_idx(a,b)][3*lane];                   \
            sp[0] = ux*s + fa*Hx[b] + fb*Hx[a];                                \
            sp[1] = uy*s + fa*Hy[b] + fb*Hy[a];                                \
            sp[2] = uz*s + fa*Hz[b] + fb*Hz[a];                                \
            pb *= r2;                                                          \
        }                                                                      \
        pa *= r2;                                                              \
    }                                                                          \
    __syncwarp();                                                              \
    /* warp-private float4 write-out of 36 streams (96 floats each) */         \
    {                                                                          \
        float* lbase = out + 252 + (size_t)(lv*36)*stride                      \
                     + (size_t)blockIdx.x*(TPB2*3) + warp*96;                  \
        _Pragma("unroll")                                                      \
        for (int k = 0; k < 27; k++){                                          \
            const int e = lane + k*32;          /* 0..863 float4s */           \
            const int s36 = e / 24;                                            \
            const int q   = e - s36*24;                                        \
            const int a = s36 / 6, b2 = s36 % 6;                               \
            const int p = (a <= b2) ? pair_idx(a,b2) : pair_idx(b2,a);         \
            const float4 v = *(const float4*)&stage[warp][p][q*4];             \
            __stcs((float4*)(lbase + (size_t)s36*stride) + q, v);              \
        }                                                                      \
    }                                                                          \
} while(0)

__global__ void __launch_bounds__(TPB2) pass2(const float* __restrict__ xyz,
                                              float* __restrict__ out){
    __shared__ __align__(16) float stage[TPB2/32][21][96];
    __shared__ float4 coefsh[LL*NM*LL*2];
    const int t = threadIdx.x;
    const int warp = t >> 5, lane = t & 31;
    for (int i = t; i < LL*NM*LL*2; i += TPB2) coefsh[i] = g_coef4[i];
    __syncthreads();

    const int j = blockIdx.x * TPB2 + t;
    const float x = xyz[3*j+0], y = xyz[3*j+1], z = xyz[3*j+2];
    const float r2 = x*x + y*y + z*z;
    const float invd = rsqrtf(r2);
    const float d = r2 * invd;
    const float ux = x*invd, uy = y*invd, uz = z*invd;

    const float tc = 1.0f - d*RCINV;
    const bool  in = (d < RCF);
    const float rcut = in ? tc*tc : 0.0f;
    const float drc  = in ? (-2.0f*RCINV)*tc : 0.0f;

    const size_t stride = (size_t)3 * NATOMS;

    float RA[LL], IA[LL], RB[LL], IB[LL];
    #pragma unroll
    for (int m = 0; m < LL; m++){ RA[m]=0.f; IA[m]=0.f; RB[m]=0.f; IB[m]=0.f; }
    RA[0] = 0.28209479177387814f;
    D_EMIT2(0, RA, IA, RB, IB);

    {
        const float sq3 = 1.7320508075688772f;
        RB[0] = z*RA[0]*sq3;
        IB[0] = 0.0f;
        const float alc = -1.2247448713915890f;
        RB[1] = alc*(x*RA[0]);
        IB[1] = alc*(y*RA[0]);
    }
    D_EMIT2(1, RB, IB, RA, IA);

    V_STEP(2, RB, IB, RA, IA); D_EMIT2(2, RA, IA, RB, IB);
    V_STEP(3, RA, IA, RB, IB); D_EMIT2(3, RB, IB, RA, IA);
    V_STEP(4, RB, IB, RA, IA); D_EMIT2(4, RA, IA, RB, IB);
    V_STEP(5, RA, IA, RB, IB); D_EMIT2(5, RB, IB, RA, IA);
    V_STEP(6, RB, IB, RA, IA); D_EMIT2(6, RA, IA, RB, IB);
}

// ---------------------------------------------------------------------------
extern "C" void kernel_launch(void* const* d_in, const int* in_sizes, int n_in,
                              void* d_out, int out_size){
    const float* xyz = (const float*)d_in[0];
    float* out = (float*)d_out;
    pass1<<<NBLK1, TPB1>>>(xyz);
    reduce_c<<<1, 1024>>>(out);
    pass2<<<NBLK2, TPB2>>>(xyz, out);
}

// round 9
// speedup vs baseline: 1.0638x; 1.0638x over previous
#include <cuda_runtime.h>
#include <math.h>

#define NATOMS 65536
#define NM     6
#define LL     7
#define NC     (NM*LL*LL)   // 294
#define RCF    6.0f
#define RCINV  (1.0f/6.0f)

// pass1: 2 threads per atom, 64 atoms per 128-thread block
#define TPB1   128
#define APB    64
#define NBLK1  (NATOMS/APB)   // 1024

// pass2: 1 atom per thread, 128 atoms per block; grid doubled for l-split
#define TPB2   128
#define NBLK2  (NATOMS/TPB2)  // 512 atom-blocks; launch 2*NBLK2

__device__ float g_part[NBLK1 * NC];
__device__ float g_c[NC];

// ---------------------------------------------------------------------------
// Value-row recursion step: dest holds row lv-2, overwritten in place.
// ---------------------------------------------------------------------------
#define V_STEP(lv, RS, IS, RD, ID) do {                                        \
    _Pragma("unroll")                                                          \
    for (int m = 0; m < lv-1; m++){                                            \
        const float invA =                                                     \
            rsqrtf((float)(lv*lv - m*m)/((2.0f*lv-1.0f)*(2.0f*lv+1.0f)));      \
        const float Ap = sqrtf((float)((lv-1)*(lv-1) - m*m)/                   \
                               ((2.0f*lv-3.0f)*(2.0f*lv-1.0f)));               \
        const float o_r = RD[m], o_i = ID[m];                                  \
        RD[m] = (z*RS[m] - Ap*r2*o_r)*invA;                                    \
        ID[m] = (z*IS[m] - Ap*r2*o_i)*invA;                                    \
    }                                                                          \
    {   const int m = lv-1;                                                    \
        const float invA =                                                     \
            rsqrtf((float)(lv*lv - m*m)/((2.0f*lv-1.0f)*(2.0f*lv+1.0f)));      \
        RD[m] = z*RS[m]*invA;                                                  \
        ID[m] = z*IS[m]*invA;                                                  \
    }                                                                          \
    {   const float alc = -sqrtf((2.0f*lv + 1.0f)/(2.0f*lv));                  \
        RD[lv] = alc*(x*RS[lv-1] - y*IS[lv-1]);                                \
        ID[lv] = alc*(x*IS[lv-1] + y*RS[lv-1]);                                \
    }                                                                          \
} while(0)

// ---------------------------------------------------------------------------
// Pass 1: values-only recursion; single-stage warp reduction (16 partials).
// ---------------------------------------------------------------------------
#define P1_RED(val, idx) do {                                                  \
    float _v = (val);                                                          \
    _v += __shfl_xor_sync(0xffffffffu, _v, 16);                                \
    if (lane < 16) wsh[wloc][lane][idx] = _v;                                  \
} while(0)

#define V_EMIT(lv, RD, ID) do {                                                \
    _Pragma("unroll")                                                          \
    for (int m = 0; m <= lv; m++){                                             \
        const float yv = RD[m];                                                \
        _Pragma("unroll")                                                      \
        for (int bb = 0; bb < 3; bb++)                                         \
            P1_RED(fh[bb]*yv, vb + bb*49 + lv*7 + (lv-m));                     \
    }                                                                          \
    _Pragma("unroll")                                                          \
    for (int m = 1; m <= lv; m++){                                             \
        const float yv = ID[m];                                                \
        _Pragma("unroll")                                                      \
        for (int bb = 0; bb < 3; bb++)                                         \
            P1_RED(fh[bb]*yv, vb + bb*49 + (m-1)*7 + lv);                      \
    }                                                                          \
} while(0)

__global__ void __launch_bounds__(TPB1) pass1(const float* __restrict__ xyz){
    __shared__ float wsh[2][16][NC];
    const int t    = threadIdx.x;
    const int lane = t & 31;
    const int half = t >> 6;
    const int al   = t & 63;
    const int wloc = al >> 5;
    const int vb   = half*3*49;
    const int j = blockIdx.x * APB + al;

    const float x = xyz[3*j+0], y = xyz[3*j+1], z = xyz[3*j+2];
    const float r2 = x*x + y*y + z*z;
    const float d  = sqrtf(r2);
    const float tc = 1.0f - d*RCINV;
    const float rcut = (d < RCF) ? tc*tc : 0.0f;

    float fh[3];
    {
        const float r6 = r2*r2*r2;
        fh[0] = rcut * (half ? r6 : 1.0f);
        fh[1] = fh[0]*r2;
        fh[2] = fh[1]*r2;
    }

    float RA[LL], IA[LL], RB[LL], IB[LL];
    RA[0] = 0.28209479177387814f; IA[0] = 0.0f;
    V_EMIT(0, RA, IA);
    {
        const float sq3 = 1.7320508075688772f;
        RB[0] = z*RA[0]*sq3;
        IB[0] = 0.0f;
        const float alc = -1.2247448713915890f;
        RB[1] = alc*(x*RA[0]);
        IB[1] = alc*(y*RA[0]);
    }
    V_EMIT(1, RB, IB);
    V_STEP(2, RB, IB, RA, IA); V_EMIT(2, RA, IA);
    V_STEP(3, RA, IA, RB, IB); V_EMIT(3, RB, IB);
    V_STEP(4, RB, IB, RA, IA); V_EMIT(4, RA, IA);
    V_STEP(5, RA, IA, RB, IB); V_EMIT(5, RB, IB);
    V_STEP(6, RB, IB, RA, IA); V_EMIT(6, RA, IA);

    __syncthreads();
    for (int v = t; v < NC; v += TPB1){
        float s = 0.0f;
        #pragma unroll
        for (int w = 0; w < 2; w++)
            #pragma unroll
            for (int c = 0; c < 16; c++)
                s += wsh[w][c][v];
        g_part[blockIdx.x*NC + v] = s;
    }
}

// ---------------------------------------------------------------------------
// Reduce 1024 partials -> c, compute p. One block.
// ---------------------------------------------------------------------------
__global__ void __launch_bounds__(1024) reduce_c(float* __restrict__ out){
    __shared__ float part3[NC*3];
    __shared__ float csh[NC];
    const int t = threadIdx.x;
    if (t < NC*3){
        const int o = t/3, s = t%3;
        float sum = 0.0f;
        for (int p = s; p < NBLK1; p += 3) sum += g_part[p*NC + o];
        part3[t] = sum;
    }
    __syncthreads();
    if (t < NC){
        const float s = part3[t*3] + part3[t*3+1] + part3[t*3+2];
        g_c[t] = s;
        csh[t] = s;
    }
    __syncthreads();
    if (t < LL*NM*NM){   // 252
        const int l = t / 36;
        const int a = (t / 6) % 6;
        const int b = t % 6;
        const float* ca = &csh[a*49];
        const float* cb = &csh[b*49];
        float s = 0.0f;
        for (int m = 0; m <= l; m++){
            const float w = (m == l) ? 1.0f : 2.0f;
            s += w * ca[l*7 + m] * cb[l*7 + m];
        }
        for (int lp = 0; lp < l; lp++){
            s += 2.0f * ca[lp*7 + l] * cb[lp*7 + l];
        }
        out[t] = s;
    }
}

// ---------------------------------------------------------------------------
// Pass 2: values-only ping-pong recursion; gradients synthesized from row l-1
// with compile-time constants; smem staging -> float4 streaming stores.
// Grid doubled: group 0 emits l in {0,5,6}, group 1 emits l in {1,2,3,4}.
// ---------------------------------------------------------------------------
__device__ __forceinline__ int pair_idx(int a, int b){
    return a*6 - (a*(a+1))/2 + b;
}

// compile-time group of each l
#define LGRP(lv) ((lv)==0 || (lv)==5 || (lv)==6 ? 0 : 1)

#define D_EMIT(lv, CR, CI, PR, PI) if (grp == LGRP(lv)) {                      \
    float G[6]={0,0,0,0,0,0}, Hx[6]={0,0,0,0,0,0},                             \
          Hy[6]={0,0,0,0,0,0}, Hz[6]={0,0,0,0,0,0};                            \
    _Pragma("unroll")                                                          \
    for (int m = 0; m <= lv; m++){                                             \
        const float az  = (m <= lv-1)                                          \
            ? sqrtf((float)((lv-m)*(lv+m))*(2.0f*lv+1.0f)/(2.0f*lv-1.0f))      \
            : 0.0f;                                                            \
        const float apH = (m+1 <= lv-1)                                        \
            ? 0.5f*sqrtf((float)((lv-m)*(lv-m-1))*(2.0f*lv+1.0f)/(2.0f*lv-1.0f))\
            : 0.0f;                                                            \
        const float amH = (lv >= 1 && (m >= 1 || lv >= 2))                     \
            ? 0.5f*sqrtf((float)((lv+m)*(lv+m-1))*(2.0f*lv+1.0f)/(2.0f*lv-1.0f))\
            : 0.0f;                                                            \
        const float prp = (m+1 <= lv-1) ? PR[m+1] : 0.0f;                      \
        const float pip = (m+1 <= lv-1) ? PI[m+1] : 0.0f;                      \
        const float prm = (m >= 1) ? PR[m-1] : ((lv >= 2) ? -PR[1] : 0.0f);    \
        const float pim = (m >= 1) ? PI[m-1] : ((lv >= 2) ?  PI[1] : 0.0f);    \
        const float pzr = (m <= lv-1) ? PR[m] : 0.0f;                          \
        const float pzi = (m <= lv-1) ? PI[m] : 0.0f;                          \
        const float gzr = az*pzr,                 gzi = az*pzi;                \
        const float gxr = apH*prp - amH*prm,      gxi = apH*pip - amH*pim;     \
        const float gyr = apH*pip + amH*pim,      gyi = -(apH*prp + amH*prm);  \
        const float w = (m == 0) ? 1.0f : 2.0f;                                \
        _Pragma("unroll")                                                      \
        for (int b = 0; b < 6; b++){                                           \
            const float wr = w * csh[b*49 + lv*7 + (lv - m)];                  \
            G[b]  += wr*CR[m]; Hx[b] += wr*gxr;                                \
            Hy[b] += wr*gyr;   Hz[b] += wr*gzr;                                \
        }                                                                      \
        if (m >= 1){                                                           \
            _Pragma("unroll")                                                  \
            for (int b = 0; b < 6; b++){                                       \
                const float wi = 2.0f * csh[b*49 + (m-1)*7 + lv];              \
                G[b]  += wi*CI[m]; Hx[b] += wi*gxi;                            \
                Hy[b] += wi*gyi;   Hz[b] += wi*gzi;                            \
            }                                                                  \
        }                                                                      \
    }                                                                          \
    /* stage 21 unique pairs into shared */                                    \
    float pa = 1.0f;                                                           \
    _Pragma("unroll")                                                          \
    for (int a = 0; a < 6; a++){                                               \
        const float fa  = rcut*pa;                                             \
        const float dca = pa*(drc + (2.0f*a)*rcut*invd);                       \
        float pb = pa;                                                         \
        _Pragma("unroll")                                                      \
        for (int b = a; b < 6; b++){                                           \
            const float fb  = rcut*pb;                                         \
            const float dcb = pb*(drc + (2.0f*b)*rcut*invd);                   \
            const float s  = dca*G[b] + dcb*G[a];                              \
            float* sp = &stage[pair_idx(a,b)][3*t];                            \
            sp[0] = ux*s + fa*Hx[b] + fb*Hx[a];                                \
            sp[1] = uy*s + fa*Hy[b] + fb*Hy[a];                                \
            sp[2] = uz*s + fa*Hz[b] + fb*Hz[a];                                \
            pb *= r2;                                                          \
        }                                                                      \
        pa *= r2;                                                              \
    }                                                                          \
    __syncthreads();                                                           \
    /* cooperative aligned float4 streaming write-out of 36 streams */         \
    {                                                                          \
        float* lbase = out + 252 + (size_t)(lv*36)*stride + (size_t)ablk*(TPB2*3); \
        _Pragma("unroll")                                                      \
        for (int k = 0; k < 27; k++){                                          \
            const int e = t + k*TPB2;            /* 0..3455 */                 \
            const int s36 = e / 96;                                            \
            const int q   = e - s36*96;                                        \
            const int a = s36 / 6, b2 = s36 % 6;                               \
            const int p = (a <= b2) ? pair_idx(a,b2) : pair_idx(b2,a);         \
            const float4 v = *(const float4*)&stage[p][q*4];                   \
            __stcs((float4*)(lbase + (size_t)s36*stride) + q, v);              \
        }                                                                      \
    }                                                                          \
    __syncthreads();                                                           \
}

__global__ void __launch_bounds__(TPB2) pass2(const float* __restrict__ xyz,
                                              float* __restrict__ out){
    __shared__ __align__(16) float stage[21][TPB2*3];
    __shared__ float csh[NC];
    const int t = threadIdx.x;
    const int grp  = blockIdx.x >> 9;          // 0: l in {0,5,6}; 1: l in {1,2,3,4}
    const int ablk = blockIdx.x & (NBLK2-1);   // atom block
    for (int i = t; i < NC; i += TPB2) csh[i] = g_c[i];
    __syncthreads();

    const int j = ablk * TPB2 + t;
    const float x = xyz[3*j+0], y = xyz[3*j+1], z = xyz[3*j+2];
    const float r2 = x*x + y*y + z*z;
    const float invd = rsqrtf(r2);
    const float d = r2 * invd;
    const float ux = x*invd, uy = y*invd, uz = z*invd;

    const float tc = 1.0f - d*RCINV;
    const bool  in = (d < RCF);
    const float rcut = in ? tc*tc : 0.0f;
    const float drc  = in ? (-2.0f*RCINV)*tc : 0.0f;

    const size_t stride = (size_t)3 * NATOMS;

    float RA[LL], IA[LL], RB[LL], IB[LL];
    RA[0] = 0.28209479177387814f; IA[0] = 0.0f;
    D_EMIT(0, RA, IA, RB, IB);

    {
        const float sq3 = 1.7320508075688772f;
        RB[0] = z*RA[0]*sq3;
        IB[0] = 0.0f;
        const float alc = -1.2247448713915890f;
        RB[1] = alc*(x*RA[0]);
        IB[1] = alc*(y*RA[0]);
    }
    D_EMIT(1, RB, IB, RA, IA);

    V_STEP(2, RB, IB, RA, IA); D_EMIT(2, RA, IA, RB, IB);
    V_STEP(3, RA, IA, RB, IB); D_EMIT(3, RB, IB, RA, IA);
    V_STEP(4, RB, IB, RA, IA); D_EMIT(4, RA, IA, RB, IB);
    V_STEP(5, RA, IA, RB, IB); D_EMIT(5, RB, IB, RA, IA);
    V_STEP(6, RB, IB, RA, IA); D_EMIT(6, RA, IA, RB, IB);
}

// ---------------------------------------------------------------------------
extern "C" void kernel_launch(void* const* d_in, const int* in_sizes, int n_in,
                              void* d_out, int out_size){
    const float* xyz = (const float*)d_in[0];
    float* out = (float*)d_out;
    pass1<<<NBLK1, TPB1>>>(xyz);
    reduce_c<<<1, 1024>>>(out);
    pass2<<<2*NBLK2, TPB2>>>(xyz, out);
}

// round 10
// speedup vs baseline: 1.3443x; 1.2638x over previous
#include <cuda_runtime.h>
#include <math.h>

#define NATOMS 65536
#define NM     6
#define LL     7
#define NC     (NM*LL*LL)   // 294
#define RCF    6.0f
#define RCINV  (1.0f/6.0f)

// pass1: 2 threads per atom, 64 atoms per 128-thread block
#define TPB1   128
#define APB    64
#define NBLK1  (NATOMS/APB)   // 1024

// pass2: 1 atom per thread, 128 atoms per block
#define TPB2   128
#define NBLK2  (NATOMS/TPB2)  // 512

__device__ float g_part[NBLK1 * NC];
__device__ float g_c[NC];

// ---------------------------------------------------------------------------
// Value-row recursion step: dest holds row lv-2, overwritten in place.
// ---------------------------------------------------------------------------
#define V_STEP(lv, RS, IS, RD, ID) do {                                        \
    _Pragma("unroll")                                                          \
    for (int m = 0; m < lv-1; m++){                                            \
        const float invA =                                                     \
            rsqrtf((float)(lv*lv - m*m)/((2.0f*lv-1.0f)*(2.0f*lv+1.0f)));      \
        const float Ap = sqrtf((float)((lv-1)*(lv-1) - m*m)/                   \
                               ((2.0f*lv-3.0f)*(2.0f*lv-1.0f)));               \
        const float o_r = RD[m], o_i = ID[m];                                  \
        RD[m] = (z*RS[m] - Ap*r2*o_r)*invA;                                    \
        ID[m] = (z*IS[m] - Ap*r2*o_i)*invA;                                    \
    }                                                                          \
    {   const int m = lv-1;                                                    \
        const float invA =                                                     \
            rsqrtf((float)(lv*lv - m*m)/((2.0f*lv-1.0f)*(2.0f*lv+1.0f)));      \
        RD[m] = z*RS[m]*invA;                                                  \
        ID[m] = z*IS[m]*invA;                                                  \
    }                                                                          \
    {   const float alc = -sqrtf((2.0f*lv + 1.0f)/(2.0f*lv));                  \
        RD[lv] = alc*(x*RS[lv-1] - y*IS[lv-1]);                                \
        ID[lv] = alc*(x*IS[lv-1] + y*RS[lv-1]);                                \
    }                                                                          \
} while(0)

// ---------------------------------------------------------------------------
// Pass 1: values-only recursion; single-stage warp reduction (16 partials).
// ---------------------------------------------------------------------------
#define P1_RED(val, idx) do {                                                  \
    float _v = (val);                                                          \
    _v += __shfl_xor_sync(0xffffffffu, _v, 16);                                \
    if (lane < 16) wsh[wloc][lane][idx] = _v;                                  \
} while(0)

#define V_EMIT(lv, RD, ID) do {                                                \
    _Pragma("unroll")                                                          \
    for (int m = 0; m <= lv; m++){                                             \
        const float yv = RD[m];                                                \
        _Pragma("unroll")                                                      \
        for (int bb = 0; bb < 3; bb++)                                         \
            P1_RED(fh[bb]*yv, vb + bb*49 + lv*7 + (lv-m));                     \
    }                                                                          \
    _Pragma("unroll")                                                          \
    for (int m = 1; m <= lv; m++){                                             \
        const float yv = ID[m];                                                \
        _Pragma("unroll")                                                      \
        for (int bb = 0; bb < 3; bb++)                                         \
            P1_RED(fh[bb]*yv, vb + bb*49 + (m-1)*7 + lv);                      \
    }                                                                          \
} while(0)

__global__ void __launch_bounds__(TPB1) pass1(const float* __restrict__ xyz){
    __shared__ float wsh[2][16][NC];
    const int t    = threadIdx.x;
    const int lane = t & 31;
    const int half = t >> 6;
    const int al   = t & 63;
    const int wloc = al >> 5;
    const int vb   = half*3*49;
    const int j = blockIdx.x * APB + al;

    const float x = xyz[3*j+0], y = xyz[3*j+1], z = xyz[3*j+2];
    const float r2 = x*x + y*y + z*z;
    const float d  = sqrtf(r2);
    const float tc = 1.0f - d*RCINV;
    const float rcut = (d < RCF) ? tc*tc : 0.0f;

    float fh[3];
    {
        const float r6 = r2*r2*r2;
        fh[0] = rcut * (half ? r6 : 1.0f);
        fh[1] = fh[0]*r2;
        fh[2] = fh[1]*r2;
    }

    float RA[LL], IA[LL], RB[LL], IB[LL];
    RA[0] = 0.28209479177387814f; IA[0] = 0.0f;
    V_EMIT(0, RA, IA);
    {
        const float sq3 = 1.7320508075688772f;
        RB[0] = z*RA[0]*sq3;
        IB[0] = 0.0f;
        const float alc = -1.2247448713915890f;
        RB[1] = alc*(x*RA[0]);
        IB[1] = alc*(y*RA[0]);
    }
    V_EMIT(1, RB, IB);
    V_STEP(2, RB, IB, RA, IA); V_EMIT(2, RA, IA);
    V_STEP(3, RA, IA, RB, IB); V_EMIT(3, RB, IB);
    V_STEP(4, RB, IB, RA, IA); V_EMIT(4, RA, IA);
    V_STEP(5, RA, IA, RB, IB); V_EMIT(5, RB, IB);
    V_STEP(6, RB, IB, RA, IA); V_EMIT(6, RA, IA);

    __syncthreads();
    for (int v = t; v < NC; v += TPB1){
        float s = 0.0f;
        #pragma unroll
        for (int w = 0; w < 2; w++)
            #pragma unroll
            for (int c = 0; c < 16; c++)
                s += wsh[w][c][v];
        g_part[blockIdx.x*NC + v] = s;
    }
}

// ---------------------------------------------------------------------------
// Stage-1 reduce: one block per c-channel; 256 threads sum 1024 partials.
// ---------------------------------------------------------------------------
__global__ void __launch_bounds__(256) reduce_part(){
    const int v = blockIdx.x;
    const int t = threadIdx.x;
    float s = 0.0f;
    #pragma unroll
    for (int k = 0; k < NBLK1/256; k++)
        s += g_part[(t + k*256)*NC + v];
    s += __shfl_xor_sync(0xffffffffu, s, 16);
    s += __shfl_xor_sync(0xffffffffu, s, 8);
    s += __shfl_xor_sync(0xffffffffu, s, 4);
    s += __shfl_xor_sync(0xffffffffu, s, 2);
    s += __shfl_xor_sync(0xffffffffu, s, 1);
    __shared__ float sm[8];
    if ((t & 31) == 0) sm[t >> 5] = s;
    __syncthreads();
    if (t == 0){
        float r = 0.0f;
        #pragma unroll
        for (int w = 0; w < 8; w++) r += sm[w];
        g_c[v] = r;
    }
}

// ---------------------------------------------------------------------------
// Stage-2: compute p (first 252 outputs) from g_c. One small block.
// ---------------------------------------------------------------------------
__global__ void __launch_bounds__(256) finalize_p(float* __restrict__ out){
    __shared__ float csh[NC];
    const int t = threadIdx.x;
    for (int i = t; i < NC; i += 256) csh[i] = g_c[i];
    __syncthreads();
    if (t < LL*NM*NM){   // 252
        const int l = t / 36;
        const int a = (t / 6) % 6;
        const int b = t % 6;
        const float* ca = &csh[a*49];
        const float* cb = &csh[b*49];
        float s = 0.0f;
        for (int m = 0; m <= l; m++){
            const float w = (m == l) ? 1.0f : 2.0f;
            s += w * ca[l*7 + m] * cb[l*7 + m];
        }
        for (int lp = 0; lp < l; lp++){
            s += 2.0f * ca[lp*7 + l] * cb[lp*7 + l];
        }
        out[t] = s;
    }
}

// ---------------------------------------------------------------------------
// Pass 2: values-only ping-pong recursion; gradients synthesized from row l-1
// with compile-time constants; smem staging -> float4 streaming stores.
// ---------------------------------------------------------------------------
__device__ __forceinline__ int pair_idx(int a, int b){
    return a*6 - (a*(a+1))/2 + b;
}

#define D_EMIT(lv, CR, CI, PR, PI) do {                                        \
    float G[6]={0,0,0,0,0,0}, Hx[6]={0,0,0,0,0,0},                             \
          Hy[6]={0,0,0,0,0,0}, Hz[6]={0,0,0,0,0,0};                            \
    _Pragma("unroll")                                                          \
    for (int m = 0; m <= lv; m++){                                             \
        const float az  = (m <= lv-1)                                          \
            ? sqrtf((float)((lv-m)*(lv+m))*(2.0f*lv+1.0f)/(2.0f*lv-1.0f))      \
            : 0.0f;                                                            \
        const float apH = (m+1 <= lv-1)                                        \
            ? 0.5f*sqrtf((float)((lv-m)*(lv-m-1))*(2.0f*lv+1.0f)/(2.0f*lv-1.0f))\
            : 0.0f;                                                            \
        const float amH = (lv >= 1 && (m >= 1 || lv >= 2))                     \
            ? 0.5f*sqrtf((float)((lv+m)*(lv+m-1))*(2.0f*lv+1.0f)/(2.0f*lv-1.0f))\
            : 0.0f;                                                            \
        const float prp = (m+1 <= lv-1) ? PR[m+1] : 0.0f;                      \
        const float pip = (m+1 <= lv-1) ? PI[m+1] : 0.0f;                      \
        const float prm = (m >= 1) ? PR[m-1] : ((lv >= 2) ? -PR[1] : 0.0f);    \
        const float pim = (m >= 1) ? PI[m-1] : ((lv >= 2) ?  PI[1] : 0.0f);    \
        const float pzr = (m <= lv-1) ? PR[m] : 0.0f;                          \
        const float pzi = (m <= lv-1) ? PI[m] : 0.0f;                          \
        const float gzr = az*pzr,                 gzi = az*pzi;                \
        const float gxr = apH*prp - amH*prm,      gxi = apH*pip - amH*pim;     \
        const float gyr = apH*pip + amH*pim,      gyi = -(apH*prp + amH*prm);  \
        const float w = (m == 0) ? 1.0f : 2.0f;                                \
        _Pragma("unroll")                                                      \
        for (int b = 0; b < 6; b++){                                           \
            const float wr = w * csh[b*49 + lv*7 + (lv - m)];                  \
            G[b]  += wr*CR[m]; Hx[b] += wr*gxr;                                \
            Hy[b] += wr*gyr;   Hz[b] += wr*gzr;                                \
        }                                                                      \
        if (m >= 1){                                                           \
            _Pragma("unroll")                                                  \
            for (int b = 0; b < 6; b++){                                       \
                const float wi = 2.0f * csh[b*49 + (m-1)*7 + lv];              \
                G[b]  += wi*CI[m]; Hx[b] += wi*gxi;                            \
                Hy[b] += wi*gyi;   Hz[b] += wi*gzi;                            \
            }                                                                  \
        }                                                                      \
    }                                                                          \
    /* stage 21 unique pairs into shared */                                    \
    float pa = 1.0f;                                                           \
    _Pragma("unroll")                                                          \
    for (int a = 0; a < 6; a++){                                               \
        const float fa  = rcut*pa;                                             \
        const float dca = pa*(drc + (2.0f*a)*rcut*invd);                       \
        float pb = pa;                                                         \
        _Pragma("unroll")                                                      \
        for (int b = a; b < 6; b++){                                           \
            const float fb  = rcut*pb;                                         \
            const float dcb = pb*(drc + (2.0f*b)*rcut*invd);                   \
            const float s  = dca*G[b] + dcb*G[a];                              \
            float* sp = &stage[pair_idx(a,b)][3*t];                            \
            sp[0] = ux*s + fa*Hx[b] + fb*Hx[a];                                \
            sp[1] = uy*s + fa*Hy[b] + fb*Hy[a];                                \
            sp[2] = uz*s + fa*Hz[b] + fb*Hz[a];                                \
            pb *= r2;                                                          \
        }                                                                      \
        pa *= r2;                                                              \
    }                                                                          \
    __syncthreads();                                                           \
    /* cooperative aligned float4 streaming write-out of 36 streams */         \
    {                                                                          \
        float* lbase = out + 252 + (size_t)(lv*36)*stride + (size_t)blockIdx.x*(TPB2*3); \
        _Pragma("unroll")                                                      \
        for (int k = 0; k < 27; k++){                                          \
            const int e = t + k*TPB2;            /* 0..3455 */                 \
            const int s36 = e / 96;                                            \
            const int q   = e - s36*96;                                        \
            const int a = s36 / 6, b2 = s36 % 6;                               \
            const int p = (a <= b2) ? pair_idx(a,b2) : pair_idx(b2,a);         \
            const float4 v = *(const float4*)&stage[p][q*4];                   \
            __stcs((float4*)(lbase + (size_t)s36*stride) + q, v);              \
        }                                                                      \
    }                                                                          \
    __syncthreads();                                                           \
} while(0)

__global__ void __launch_bounds__(TPB2) pass2(const float* __restrict__ xyz,
                                              float* __restrict__ out){
    __shared__ __align__(16) float stage[21][TPB2*3];
    __shared__ float csh[NC];
    const int t = threadIdx.x;
    for (int i = t; i < NC; i += TPB2) csh[i] = g_c[i];
    __syncthreads();

    const int j = blockIdx.x * TPB2 + t;
    const float x = xyz[3*j+0], y = xyz[3*j+1], z = xyz[3*j+2];
    const float r2 = x*x + y*y + z*z;
    const float invd = rsqrtf(r2);
    const float d = r2 * invd;
    const float ux = x*invd, uy = y*invd, uz = z*invd;

    const float tc = 1.0f - d*RCINV;
    const bool  in = (d < RCF);
    const float rcut = in ? tc*tc : 0.0f;
    const float drc  = in ? (-2.0f*RCINV)*tc : 0.0f;

    const size_t stride = (size_t)3 * NATOMS;

    float RA[LL], IA[LL], RB[LL], IB[LL];
    RA[0] = 0.28209479177387814f; IA[0] = 0.0f;
    D_EMIT(0, RA, IA, RB, IB);

    {
        const float sq3 = 1.7320508075688772f;
        RB[0] = z*RA[0]*sq3;
        IB[0] = 0.0f;
        const float alc = -1.2247448713915890f;
        RB[1] = alc*(x*RA[0]);
        IB[1] = alc*(y*RA[0]);
    }
    D_EMIT(1, RB, IB, RA, IA);

    V_STEP(2, RB, IB, RA, IA); D_EMIT(2, RA, IA, RB, IB);
    V_STEP(3, RA, IA, RB, IB); D_EMIT(3, RB, IB, RA, IA);
    V_STEP(4, RB, IB, RA, IA); D_EMIT(4, RA, IA, RB, IB);
    V_STEP(5, RA, IA, RB, IB); D_EMIT(5, RB, IB, RA, IA);
    V_STEP(6, RB, IB, RA, IA); D_EMIT(6, RA, IA, RB, IB);
}

// ---------------------------------------------------------------------------
extern "C" void kernel_launch(void* const* d_in, const int* in_sizes, int n_in,
                              void* d_out, int out_size){
    const float* xyz = (const float*)d_in[0];
    float* out = (float*)d_out;
    pass1<<<NBLK1, TPB1>>>(xyz);
    reduce_part<<<NC, 256>>>();
    finalize_p<<<1, 256>>>(out);
    pass2<<<NBLK2, TPB2>>>(xyz, out);
}

// round 11
// speedup vs baseline: 1.3812x; 1.0274x over previous
#include <cuda_runtime.h>
#include <math.h>

#define NATOMS 65536
#define NM     6
#define LL     7
#define NC     (NM*LL*LL)   // 294
#define RCF    6.0f
#define RCINV  (1.0f/6.0f)

// pass1: 2 threads per atom, 64 atoms per 128-thread block
#define TPB1   128
#define APB    64
#define NBLK1  (NATOMS/APB)   // 1024

// pass2: 1 atom per thread, 128 atoms per block
#define TPB2   128
#define NBLK2  (NATOMS/TPB2)  // 512

__device__ float g_part[NBLK1 * NC];
__device__ float g_c[NC];

// ---------------------------------------------------------------------------
// Value-row recursion step: dest holds row lv-2, overwritten in place.
// ---------------------------------------------------------------------------
#define V_STEP(lv, RS, IS, RD, ID) do {                                        \
    _Pragma("unroll")                                                          \
    for (int m = 0; m < lv-1; m++){                                            \
        const float invA =                                                     \
            rsqrtf((float)(lv*lv - m*m)/((2.0f*lv-1.0f)*(2.0f*lv+1.0f)));      \
        const float Ap = sqrtf((float)((lv-1)*(lv-1) - m*m)/                   \
                               ((2.0f*lv-3.0f)*(2.0f*lv-1.0f)));               \
        const float o_r = RD[m], o_i = ID[m];                                  \
        RD[m] = (z*RS[m] - Ap*r2*o_r)*invA;                                    \
        ID[m] = (z*IS[m] - Ap*r2*o_i)*invA;                                    \
    }                                                                          \
    {   const int m = lv-1;                                                    \
        const float invA =                                                     \
            rsqrtf((float)(lv*lv - m*m)/((2.0f*lv-1.0f)*(2.0f*lv+1.0f)));      \
        RD[m] = z*RS[m]*invA;                                                  \
        ID[m] = z*IS[m]*invA;                                                  \
    }                                                                          \
    {   const float alc = -sqrtf((2.0f*lv + 1.0f)/(2.0f*lv));                  \
        RD[lv] = alc*(x*RS[lv-1] - y*IS[lv-1]);                                \
        ID[lv] = alc*(x*IS[lv-1] + y*RS[lv-1]);                                \
    }                                                                          \
} while(0)

// ---------------------------------------------------------------------------
// Pass 1: values-only recursion; single-stage warp reduction (16 partials).
// ---------------------------------------------------------------------------
#define P1_RED(val, idx) do {                                                  \
    float _v = (val);                                                          \
    _v += __shfl_xor_sync(0xffffffffu, _v, 16);                                \
    if (lane < 16) wsh[wloc][lane][idx] = _v;                                  \
} while(0)

#define V_EMIT(lv, RD, ID) do {                                                \
    _Pragma("unroll")                                                          \
    for (int m = 0; m <= lv; m++){                                             \
        const float yv = RD[m];                                                \
        _Pragma("unroll")                                                      \
        for (int bb = 0; bb < 3; bb++)                                         \
            P1_RED(fh[bb]*yv, vb + bb*49 + lv*7 + (lv-m));                     \
    }                                                                          \
    _Pragma("unroll")                                                          \
    for (int m = 1; m <= lv; m++){                                             \
        const float yv = ID[m];                                                \
        _Pragma("unroll")                                                      \
        for (int bb = 0; bb < 3; bb++)                                         \
            P1_RED(fh[bb]*yv, vb + bb*49 + (m-1)*7 + lv);                      \
    }                                                                          \
} while(0)

__global__ void __launch_bounds__(TPB1) pass1(const float* __restrict__ xyz){
    __shared__ float wsh[2][16][NC];
    const int t    = threadIdx.x;
    const int lane = t & 31;
    const int half = t >> 6;
    const int al   = t & 63;
    const int wloc = al >> 5;
    const int vb   = half*3*49;
    const int j = blockIdx.x * APB + al;

    const float x = xyz[3*j+0], y = xyz[3*j+1], z = xyz[3*j+2];
    const float r2 = x*x + y*y + z*z;
    const float d  = sqrtf(r2);
    const float tc = 1.0f - d*RCINV;
    const float rcut = (d < RCF) ? tc*tc : 0.0f;

    float fh[3];
    {
        const float r6 = r2*r2*r2;
        fh[0] = rcut * (half ? r6 : 1.0f);
        fh[1] = fh[0]*r2;
        fh[2] = fh[1]*r2;
    }

    float RA[LL], IA[LL], RB[LL], IB[LL];
    RA[0] = 0.28209479177387814f; IA[0] = 0.0f;
    V_EMIT(0, RA, IA);
    {
        const float sq3 = 1.7320508075688772f;
        RB[0] = z*RA[0]*sq3;
        IB[0] = 0.0f;
        const float alc = -1.2247448713915890f;
        RB[1] = alc*(x*RA[0]);
        IB[1] = alc*(y*RA[0]);
    }
    V_EMIT(1, RB, IB);
    V_STEP(2, RB, IB, RA, IA); V_EMIT(2, RA, IA);
    V_STEP(3, RA, IA, RB, IB); V_EMIT(3, RB, IB);
    V_STEP(4, RB, IB, RA, IA); V_EMIT(4, RA, IA);
    V_STEP(5, RA, IA, RB, IB); V_EMIT(5, RB, IB);
    V_STEP(6, RB, IB, RA, IA); V_EMIT(6, RA, IA);

    __syncthreads();
    for (int v = t; v < NC; v += TPB1){
        float s = 0.0f;
        #pragma unroll
        for (int w = 0; w < 2; w++)
            #pragma unroll
            for (int c = 0; c < 16; c++)
                s += wsh[w][c][v];
        g_part[blockIdx.x*NC + v] = s;
    }
}

// ---------------------------------------------------------------------------
// Stage-1 reduce: one block per c-channel; 256 threads sum 1024 partials.
// ---------------------------------------------------------------------------
__global__ void __launch_bounds__(256) reduce_part(){
    const int v = blockIdx.x;
    const int t = threadIdx.x;
    float s = 0.0f;
    #pragma unroll
    for (int k = 0; k < NBLK1/256; k++)
        s += g_part[(t + k*256)*NC + v];
    s += __shfl_xor_sync(0xffffffffu, s, 16);
    s += __shfl_xor_sync(0xffffffffu, s, 8);
    s += __shfl_xor_sync(0xffffffffu, s, 4);
    s += __shfl_xor_sync(0xffffffffu, s, 2);
    s += __shfl_xor_sync(0xffffffffu, s, 1);
    __shared__ float sm[8];
    if ((t & 31) == 0) sm[t >> 5] = s;
    __syncthreads();
    if (t == 0){
        float r = 0.0f;
        #pragma unroll
        for (int w = 0; w < 8; w++) r += sm[w];
        g_c[v] = r;
    }
}

// ---------------------------------------------------------------------------
// Stage-2: compute p (first 252 outputs) from g_c. One small block.
// ---------------------------------------------------------------------------
__global__ void __launch_bounds__(256) finalize_p(float* __restrict__ out){
    __shared__ float csh[NC];
    const int t = threadIdx.x;
    for (int i = t; i < NC; i += 256) csh[i] = g_c[i];
    __syncthreads();
    if (t < LL*NM*NM){   // 252
        const int l = t / 36;
        const int a = (t / 6) % 6;
        const int b = t % 6;
        const float* ca = &csh[a*49];
        const float* cb = &csh[b*49];
        float s = 0.0f;
        for (int m = 0; m <= l; m++){
            const float w = (m == l) ? 1.0f : 2.0f;
            s += w * ca[l*7 + m] * cb[l*7 + m];
        }
        for (int lp = 0; lp < l; lp++){
            s += 2.0f * ca[lp*7 + l] * cb[lp*7 + l];
        }
        out[t] = s;
    }
}

// ---------------------------------------------------------------------------
// Pass 2: values-only ping-pong recursion; gradients synthesized from row l-1
// with compile-time constants; smem staging -> float4 streaming stores.
// launch_bounds(128,5) caps regs ~102 -> 20 resident warps/SM.
// ---------------------------------------------------------------------------
__device__ __forceinline__ int pair_idx(int a, int b){
    return a*6 - (a*(a+1))/2 + b;
}

#define D_EMIT(lv, CR, CI, PR, PI) do {                                        \
    float G[6]={0,0,0,0,0,0}, Hx[6]={0,0,0,0,0,0},                             \
          Hy[6]={0,0,0,0,0,0}, Hz[6]={0,0,0,0,0,0};                            \
    _Pragma("unroll")                                                          \
    for (int m = 0; m <= lv; m++){                                             \
        const float az  = (m <= lv-1)                                          \
            ? sqrtf((float)((lv-m)*(lv+m))*(2.0f*lv+1.0f)/(2.0f*lv-1.0f))      \
            : 0.0f;                                                            \
        const float apH = (m+1 <= lv-1)                                        \
            ? 0.5f*sqrtf((float)((lv-m)*(lv-m-1))*(2.0f*lv+1.0f)/(2.0f*lv-1.0f))\
            : 0.0f;                                                            \
        const float amH = (lv >= 1 && (m >= 1 || lv >= 2))                     \
            ? 0.5f*sqrtf((float)((lv+m)*(lv+m-1))*(2.0f*lv+1.0f)/(2.0f*lv-1.0f))\
            : 0.0f;                                                            \
        const float prp = (m+1 <= lv-1) ? PR[m+1] : 0.0f;                      \
        const float pip = (m+1 <= lv-1) ? PI[m+1] : 0.0f;                      \
        const float prm = (m >= 1) ? PR[m-1] : ((lv >= 2) ? -PR[1] : 0.0f);    \
        const float pim = (m >= 1) ? PI[m-1] : ((lv >= 2) ?  PI[1] : 0.0f);    \
        const float pzr = (m <= lv-1) ? PR[m] : 0.0f;                          \
        const float pzi = (m <= lv-1) ? PI[m] : 0.0f;                          \
        const float gzr = az*pzr,                 gzi = az*pzi;                \
        const float gxr = apH*prp - amH*prm,      gxi = apH*pip - amH*pim;     \
        const float gyr = apH*pip + amH*pim,      gyi = -(apH*prp + amH*prm);  \
        const float w = (m == 0) ? 1.0f : 2.0f;                                \
        _Pragma("unroll")                                                      \
        for (int b = 0; b < 6; b++){                                           \
            const float wr = w * csh[b*49 + lv*7 + (lv - m)];                  \
            G[b]  += wr*CR[m]; Hx[b] += wr*gxr;                                \
            Hy[b] += wr*gyr;   Hz[b] += wr*gzr;                                \
        }                                                                      \
        if (m >= 1){                                                           \
            _Pragma("unroll")                                                  \
            for (int b = 0; b < 6; b++){                                       \
                const float wi = 2.0f * csh[b*49 + (m-1)*7 + lv];              \
                G[b]  += wi*CI[m]; Hx[b] += wi*gxi;                            \
                Hy[b] += wi*gyi;   Hz[b] += wi*gzi;                            \
            }                                                                  \
        }                                                                      \
    }                                                                          \
    /* stage 21 unique pairs into shared */                                    \
    float pa = 1.0f;                                                           \
    _Pragma("unroll")                                                          \
    for (int a = 0; a < 6; a++){                                               \
        const float fa  = rcut*pa;                                             \
        const float dca = pa*(drc + (2.0f*a)*rcut*invd);                       \
        float pb = pa;                                                         \
        _Pragma("unroll")                                                      \
        for (int b = a; b < 6; b++){                                           \
            const float fb  = rcut*pb;                                         \
            const float dcb = pb*(drc + (2.0f*b)*rcut*invd);                   \
            const float s  = dca*G[b] + dcb*G[a];                              \
            float* sp = &stage[pair_idx(a,b)][3*t];                            \
            sp[0] = ux*s + fa*Hx[b] + fb*Hx[a];                                \
            sp[1] = uy*s + fa*Hy[b] + fb*Hy[a];                                \
            sp[2] = uz*s + fa*Hz[b] + fb*Hz[a];                                \
            pb *= r2;                                                          \
        }                                                                      \
        pa *= r2;                                                              \
    }                                                                          \
    __syncthreads();                                                           \
    /* cooperative aligned float4 streaming write-out of 36 streams */         \
    {                                                                          \
        float* lbase = out + 252 + (size_t)(lv*36)*stride + (size_t)blockIdx.x*(TPB2*3); \
        _Pragma("unroll 3")                                                    \
        for (int k = 0; k < 27; k++){                                          \
            const int e = t + k*TPB2;            /* 0..3455 */                 \
            const int s36 = e / 96;                                            \
            const int q   = e - s36*96;                                        \
            const int a = s36 / 6, b2 = s36 % 6;                               \
            const int p = (a <= b2) ? pair_idx(a,b2) : pair_idx(b2,a);         \
            const float4 v = *(const float4*)&stage[p][q*4];                   \
            __stcs((float4*)(lbase + (size_t)s36*stride) + q, v);              \
        }                                                                      \
    }                                                                          \
    __syncthreads();                                                           \
} while(0)

__global__ void __launch_bounds__(TPB2, 5) pass2(const float* __restrict__ xyz,
                                                 float* __restrict__ out){
    __shared__ __align__(16) float stage[21][TPB2*3];
    __shared__ float csh[NC];
    const int t = threadIdx.x;
    for (int i = t; i < NC; i += TPB2) csh[i] = g_c[i];
    __syncthreads();

    const int j = blockIdx.x * TPB2 + t;
    const float x = xyz[3*j+0], y = xyz[3*j+1], z = xyz[3*j+2];
    const float r2 = x*x + y*y + z*z;
    const float invd = rsqrtf(r2);
    const float d = r2 * invd;
    const float ux = x*invd, uy = y*invd, uz = z*invd;

    const float tc = 1.0f - d*RCINV;
    const bool  in = (d < RCF);
    const float rcut = in ? tc*tc : 0.0f;
    const float drc  = in ? (-2.0f*RCINV)*tc : 0.0f;

    const size_t stride = (size_t)3 * NATOMS;

    float RA[LL], IA[LL], RB[LL], IB[LL];
    RA[0] = 0.28209479177387814f; IA[0] = 0.0f;
    D_EMIT(0, RA, IA, RB, IB);

    {
        const float sq3 = 1.7320508075688772f;
        RB[0] = z*RA[0]*sq3;
        IB[0] = 0.0f;
        const float alc = -1.2247448713915890f;
        RB[1] = alc*(x*RA[0]);
        IB[1] = alc*(y*RA[0]);
    }
    D_EMIT(1, RB, IB, RA, IA);

    V_STEP(2, RB, IB, RA, IA); D_EMIT(2, RA, IA, RB, IB);
    V_STEP(3, RA, IA, RB, IB); D_EMIT(3, RB, IB, RA, IA);
    V_STEP(4, RB, IB, RA, IA); D_EMIT(4, RA, IA, RB, IB);
    V_STEP(5, RA, IA, RB, IB); D_EMIT(5, RB, IB, RA, IA);
    V_STEP(6, RB, IB, RA, IA); D_EMIT(6, RA, IA, RB, IB);
}

// ---------------------------------------------------------------------------
extern "C" void kernel_launch(void* const* d_in, const int* in_sizes, int n_in,
                              void* d_out, int out_size){
    const float* xyz = (const float*)d_in[0];
    float* out = (float*)d_out;
    pass1<<<NBLK1, TPB1>>>(xyz);
    reduce_part<<<NC, 256>>>();
    finalize_p<<<1, 256>>>(out);
    pass2<<<NBLK2, TPB2>>>(xyz, out);
}

// round 12
// speedup vs baseline: 1.4280x; 1.0339x over previous
#include <cuda_runtime.h>
#include <math.h>

#define NATOMS 65536
#define NM     6
#define LL     7
#define NC     (NM*LL*LL)   // 294
#define RCF    6.0f
#define RCINV  (1.0f/6.0f)

// pass1: 2 threads per atom, 64 atoms per 128-thread block
#define TPB1   128
#define APB    64
#define NBLK1  (NATOMS/APB)   // 1024

// pass2: 1 atom per thread, 128 atoms per block; grid doubled by l-split
#define TPB2   128
#define NBLK2  (NATOMS/TPB2)  // 512 atom-blocks; launch 2*NBLK2

__device__ float g_part[NBLK1 * NC];
__device__ float g_c[NC];

// ---------------------------------------------------------------------------
// Value-row recursion step: dest holds row lv-2, overwritten in place.
// ---------------------------------------------------------------------------
#define V_STEP(lv, RS, IS, RD, ID) do {                                        \
    _Pragma("unroll")                                                          \
    for (int m = 0; m < lv-1; m++){                                            \
        const float invA =                                                     \
            rsqrtf((float)(lv*lv - m*m)/((2.0f*lv-1.0f)*(2.0f*lv+1.0f)));      \
        const float Ap = sqrtf((float)((lv-1)*(lv-1) - m*m)/                   \
                               ((2.0f*lv-3.0f)*(2.0f*lv-1.0f)));               \
        const float o_r = RD[m], o_i = ID[m];                                  \
        RD[m] = (z*RS[m] - Ap*r2*o_r)*invA;                                    \
        ID[m] = (z*IS[m] - Ap*r2*o_i)*invA;                                    \
    }                                                                          \
    {   const int m = lv-1;                                                    \
        const float invA =                                                     \
            rsqrtf((float)(lv*lv - m*m)/((2.0f*lv-1.0f)*(2.0f*lv+1.0f)));      \
        RD[m] = z*RS[m]*invA;                                                  \
        ID[m] = z*IS[m]*invA;                                                  \
    }                                                                          \
    {   const float alc = -sqrtf((2.0f*lv + 1.0f)/(2.0f*lv));                  \
        RD[lv] = alc*(x*RS[lv-1] - y*IS[lv-1]);                                \
        ID[lv] = alc*(x*IS[lv-1] + y*RS[lv-1]);                                \
    }                                                                          \
} while(0)

// ---------------------------------------------------------------------------
// Pass 1: values-only recursion; single-stage warp reduction (16 partials).
// ---------------------------------------------------------------------------
#define P1_RED(val, idx) do {                                                  \
    float _v = (val);                                                          \
    _v += __shfl_xor_sync(0xffffffffu, _v, 16);                                \
    if (lane < 16) wsh[wloc][lane][idx] = _v;                                  \
} while(0)

#define V_EMIT(lv, RD, ID) do {                                                \
    _Pragma("unroll")                                                          \
    for (int m = 0; m <= lv; m++){                                             \
        const float yv = RD[m];                                                \
        _Pragma("unroll")                                                      \
        for (int bb = 0; bb < 3; bb++)                                         \
            P1_RED(fh[bb]*yv, vb + bb*49 + lv*7 + (lv-m));                     \
    }                                                                          \
    _Pragma("unroll")                                                          \
    for (int m = 1; m <= lv; m++){                                             \
        const float yv = ID[m];                                                \
        _Pragma("unroll")                                                      \
        for (int bb = 0; bb < 3; bb++)                                         \
            P1_RED(fh[bb]*yv, vb + bb*49 + (m-1)*7 + lv);                      \
    }                                                                          \
} while(0)

__global__ void __launch_bounds__(TPB1) pass1(const float* __restrict__ xyz){
    __shared__ float wsh[2][16][NC];
    const int t    = threadIdx.x;
    const int lane = t & 31;
    const int half = t >> 6;
    const int al   = t & 63;
    const int wloc = al >> 5;
    const int vb   = half*3*49;
    const int j = blockIdx.x * APB + al;

    const float x = xyz[3*j+0], y = xyz[3*j+1], z = xyz[3*j+2];
    const float r2 = x*x + y*y + z*z;
    const float d  = sqrtf(r2);
    const float tc = 1.0f - d*RCINV;
    const float rcut = (d < RCF) ? tc*tc : 0.0f;

    float fh[3];
    {
        const float r6 = r2*r2*r2;
        fh[0] = rcut * (half ? r6 : 1.0f);
        fh[1] = fh[0]*r2;
        fh[2] = fh[1]*r2;
    }

    float RA[LL], IA[LL], RB[LL], IB[LL];
    RA[0] = 0.28209479177387814f; IA[0] = 0.0f;
    V_EMIT(0, RA, IA);
    {
        const float sq3 = 1.7320508075688772f;
        RB[0] = z*RA[0]*sq3;
        IB[0] = 0.0f;
        const float alc = -1.2247448713915890f;
        RB[1] = alc*(x*RA[0]);
        IB[1] = alc*(y*RA[0]);
    }
    V_EMIT(1, RB, IB);
    V_STEP(2, RB, IB, RA, IA); V_EMIT(2, RA, IA);
    V_STEP(3, RA, IA, RB, IB); V_EMIT(3, RB, IB);
    V_STEP(4, RB, IB, RA, IA); V_EMIT(4, RA, IA);
    V_STEP(5, RA, IA, RB, IB); V_EMIT(5, RB, IB);
    V_STEP(6, RB, IB, RA, IA); V_EMIT(6, RA, IA);

    __syncthreads();
    for (int v = t; v < NC; v += TPB1){
        float s = 0.0f;
        #pragma unroll
        for (int w = 0; w < 2; w++)
            #pragma unroll
            for (int c = 0; c < 16; c++)
                s += wsh[w][c][v];
        g_part[blockIdx.x*NC + v] = s;
    }
}

// ---------------------------------------------------------------------------
// Stage-1 reduce: one block per c-channel; 256 threads sum 1024 partials.
// ---------------------------------------------------------------------------
__global__ void __launch_bounds__(256) reduce_part(){
    const int v = blockIdx.x;
    const int t = threadIdx.x;
    float s = 0.0f;
    #pragma unroll
    for (int k = 0; k < NBLK1/256; k++)
        s += g_part[(t + k*256)*NC + v];
    s += __shfl_xor_sync(0xffffffffu, s, 16);
    s += __shfl_xor_sync(0xffffffffu, s, 8);
    s += __shfl_xor_sync(0xffffffffu, s, 4);
    s += __shfl_xor_sync(0xffffffffu, s, 2);
    s += __shfl_xor_sync(0xffffffffu, s, 1);
    __shared__ float sm[8];
    if ((t & 31) == 0) sm[t >> 5] = s;
    __syncthreads();
    if (t == 0){
        float r = 0.0f;
        #pragma unroll
        for (int w = 0; w < 8; w++) r += sm[w];
        g_c[v] = r;
    }
}

// ---------------------------------------------------------------------------
// Stage-2: compute p (first 252 outputs) from g_c. One small block.
// ---------------------------------------------------------------------------
__global__ void __launch_bounds__(256) finalize_p(float* __restrict__ out){
    __shared__ float csh[NC];
    const int t = threadIdx.x;
    for (int i = t; i < NC; i += 256) csh[i] = g_c[i];
    __syncthreads();
    if (t < LL*NM*NM){   // 252
        const int l = t / 36;
        const int a = (t / 6) % 6;
        const int b = t % 6;
        const float* ca = &csh[a*49];
        const float* cb = &csh[b*49];
        float s = 0.0f;
        for (int m = 0; m <= l; m++){
            const float w = (m == l) ? 1.0f : 2.0f;
            s += w * ca[l*7 + m] * cb[l*7 + m];
        }
        for (int lp = 0; lp < l; lp++){
            s += 2.0f * ca[lp*7 + l] * cb[lp*7 + l];
        }
        out[t] = s;
    }
}

// ---------------------------------------------------------------------------
// Pass 2: values-only ping-pong recursion; gradients synthesized from row l-1;
// smem staging -> float4 streaming stores. Grid doubled by l-split:
// group 0 emits l in {0,5,6}; group 1 emits l in {1,2,3,4}.
// ---------------------------------------------------------------------------
__device__ __forceinline__ int pair_idx(int a, int b){
    return a*6 - (a*(a+1))/2 + b;
}

#define LGRP(lv) ((lv)==0 || (lv)==5 || (lv)==6 ? 0 : 1)

#define D_EMIT(lv, CR, CI, PR, PI) if (grp == LGRP(lv)) {                      \
    float G[6]={0,0,0,0,0,0}, Hx[6]={0,0,0,0,0,0},                             \
          Hy[6]={0,0,0,0,0,0}, Hz[6]={0,0,0,0,0,0};                            \
    _Pragma("unroll")                                                          \
    for (int m = 0; m <= lv; m++){                                             \
        const float az  = (m <= lv-1)                                          \
            ? sqrtf((float)((lv-m)*(lv+m))*(2.0f*lv+1.0f)/(2.0f*lv-1.0f))      \
            : 0.0f;                                                            \
        const float apH = (m+1 <= lv-1)                                        \
            ? 0.5f*sqrtf((float)((lv-m)*(lv-m-1))*(2.0f*lv+1.0f)/(2.0f*lv-1.0f))\
            : 0.0f;                                                            \
        const float amH = (lv >= 1 && (m >= 1 || lv >= 2))                     \
            ? 0.5f*sqrtf((float)((lv+m)*(lv+m-1))*(2.0f*lv+1.0f)/(2.0f*lv-1.0f))\
            : 0.0f;                                                            \
        const float prp = (m+1 <= lv-1) ? PR[m+1] : 0.0f;                      \
        const float pip = (m+1 <= lv-1) ? PI[m+1] : 0.0f;                      \
        const float prm = (m >= 1) ? PR[m-1] : ((lv >= 2) ? -PR[1] : 0.0f);    \
        const float pim = (m >= 1) ? PI[m-1] : ((lv >= 2) ?  PI[1] : 0.0f);    \
        const float pzr = (m <= lv-1) ? PR[m] : 0.0f;                          \
        const float pzi = (m <= lv-1) ? PI[m] : 0.0f;                          \
        const float gzr = az*pzr,                 gzi = az*pzi;                \
        const float gxr = apH*prp - amH*prm,      gxi = apH*pip - amH*pim;     \
        const float gyr = apH*pip + amH*pim,      gyi = -(apH*prp + amH*prm);  \
        const float w = (m == 0) ? 1.0f : 2.0f;                                \
        _Pragma("unroll")                                                      \
        for (int b = 0; b < 6; b++){                                           \
            const float wr = w * csh[b*49 + lv*7 + (lv - m)];                  \
            G[b]  += wr*CR[m]; Hx[b] += wr*gxr;                                \
            Hy[b] += wr*gyr;   Hz[b] += wr*gzr;                                \
        }                                                                      \
        if (m >= 1){                                                           \
            _Pragma("unroll")                                                  \
            for (int b = 0; b < 6; b++){                                       \
                const float wi = 2.0f * csh[b*49 + (m-1)*7 + lv];              \
                G[b]  += wi*CI[m]; Hx[b] += wi*gxi;                            \
                Hy[b] += wi*gyi;   Hz[b] += wi*gzi;                            \
            }                                                                  \
        }                                                                      \
    }                                                                          \
    /* stage 21 unique pairs into shared */                                    \
    float pa = 1.0f;                                                           \
    _Pragma("unroll")                                                          \
    for (int a = 0; a < 6; a++){                                               \
        const float fa  = rcut*pa;                                             \
        const float dca = pa*(drc + (2.0f*a)*rcut*invd);                       \
        float pb = pa;                                                         \
        _Pragma("unroll")                                                      \
        for (int b = a; b < 6; b++){                                           \
            const float fb  = rcut*pb;                                         \
            const float dcb = pb*(drc + (2.0f*b)*rcut*invd);                   \
            const float s  = dca*G[b] + dcb*G[a];                              \
            float* sp = &stage[pair_idx(a,b)][3*t];                            \
            sp[0] = ux*s + fa*Hx[b] + fb*Hx[a];                                \
            sp[1] = uy*s + fa*Hy[b] + fb*Hy[a];                                \
            sp[2] = uz*s + fa*Hz[b] + fb*Hz[a];                                \
            pb *= r2;                                                          \
        }                                                                      \
        pa *= r2;                                                              \
    }                                                                          \
    __syncthreads();                                                           \
    /* cooperative aligned float4 streaming write-out of 36 streams */         \
    {                                                                          \
        float* lbase = out + 252 + (size_t)(lv*36)*stride + (size_t)ablk*(TPB2*3); \
        _Pragma("unroll 3")                                                    \
        for (int k = 0; k < 27; k++){                                          \
            const int e = t + k*TPB2;            /* 0..3455 */                 \
            const int s36 = e / 96;                                            \
            const int q   = e - s36*96;                                        \
            const int a = s36 / 6, b2 = s36 % 6;                               \
            const int p = (a <= b2) ? pair_idx(a,b2) : pair_idx(b2,a);         \
            const float4 v = *(const float4*)&stage[p][q*4];                   \
            __stcs((float4*)(lbase + (size_t)s36*stride) + q, v);              \
        }                                                                      \
    }                                                                          \
    __syncthreads();                                                           \
}

__global__ void __launch_bounds__(TPB2, 5) pass2(const float* __restrict__ xyz,
                                                 float* __restrict__ out){
    __shared__ __align__(16) float stage[21][TPB2*3];
    __shared__ float csh[NC];
    const int t = threadIdx.x;
    const int grp  = blockIdx.x >> 9;          // 0: l in {0,5,6}; 1: l in {1,2,3,4}
    const int ablk = blockIdx.x & (NBLK2-1);   // atom block
    for (int i = t; i < NC; i += TPB2) csh[i] = g_c[i];
    __syncthreads();

    const int j = ablk * TPB2 + t;
    const float x = xyz[3*j+0], y = xyz[3*j+1], z = xyz[3*j+2];
    const float r2 = x*x + y*y + z*z;
    const float invd = rsqrtf(r2);
    const float d = r2 * invd;
    const float ux = x*invd, uy = y*invd, uz = z*invd;

    const float tc = 1.0f - d*RCINV;
    const bool  in = (d < RCF);
    const float rcut = in ? tc*tc : 0.0f;
    const float drc  = in ? (-2.0f*RCINV)*tc : 0.0f;

    const size_t stride = (size_t)3 * NATOMS;

    float RA[LL], IA[LL], RB[LL], IB[LL];
    RA[0] = 0.28209479177387814f; IA[0] = 0.0f;
    D_EMIT(0, RA, IA, RB, IB);

    {
        const float sq3 = 1.7320508075688772f;
        RB[0] = z*RA[0]*sq3;
        IB[0] = 0.0f;
        const float alc = -1.2247448713915890f;
        RB[1] = alc*(x*RA[0]);
        IB[1] = alc*(y*RA[0]);
    }
    D_EMIT(1, RB, IB, RA, IA);

    V_STEP(2, RB, IB, RA, IA); D_EMIT(2, RA, IA, RB, IB);
    V_STEP(3, RA, IA, RB, IB); D_EMIT(3, RB, IB, RA, IA);
    V_STEP(4, RB, IB, RA, IA); D_EMIT(4, RA, IA, RB, IB);
    V_STEP(5, RA, IA, RB, IB); D_EMIT(5, RB, IB, RA, IA);
    V_STEP(6, RB, IB, RA, IA); D_EMIT(6, RA, IA, RB, IB);
}

// ---------------------------------------------------------------------------
extern "C" void kernel_launch(void* const* d_in, const int* in_sizes, int n_in,
                              void* d_out, int out_size){
    const float* xyz = (const float*)d_in[0];
    float* out = (float*)d_out;
    pass1<<<NBLK1, TPB1>>>(xyz);
    reduce_part<<<NC, 256>>>();
    finalize_p<<<1, 256>>>(out);
    pass2<<<2*NBLK2, TPB2>>>(xyz, out);
}